// round 2
// baseline (speedup 1.0000x reference)
#include <cuda_runtime.h>
#include <cuda_bf16.h>
#include <math.h>

// ---------------------------------------------------------------------------
// Problem constants
// ---------------------------------------------------------------------------
#define BB    32
#define HH    112
#define WW2   112
#define CC    96
#define NHH   3
#define WSS   7
#define SHF   3
#define HIDD  384
#define NTOK  49              // tokens per window
#define HDD   32              // head dim
#define NWH   16              // windows per row
#define NWIN  8192            // B * 256 windows
#define MTOK  401408          // NWIN*49 == B*H*W

// ---------------------------------------------------------------------------
// Scratch (device globals; no runtime allocation allowed)
// ---------------------------------------------------------------------------
__device__ __align__(16) float g_ln1[(size_t)MTOK * CC];   // LN1(x), window-token order
__device__ __align__(16) float g_q[(size_t)NWIN * NHH * NTOK * HDD];
__device__ __align__(16) float g_k[(size_t)NWIN * NHH * NTOK * HDD];
__device__ __align__(16) float g_v[(size_t)NWIN * NHH * NTOK * HDD];
__device__ __align__(16) float g_att[(size_t)MTOK * CC];   // attn out (win-token, head*32+d)
__device__ __align__(16) float g_x1[(size_t)MTOK * CC];    // shortcut + proj (original order)
__device__ __align__(16) float g_ln2[(size_t)MTOK * CC];
__device__ __align__(16) float g_h1[(size_t)MTOK * HIDD];  // gelu(fc1)
__device__ __align__(16) float g_comb[(size_t)256 * NHH * NTOK * NTOK]; // mask + rel bias

// window-token index m -> original token row index (b*12544 + h*112 + w)
__device__ __forceinline__ int rowsrc(int m) {
    int win = m / NTOK, tok = m - win * NTOK;
    int b = win >> 8, widx = win & 255;
    int wh = widx >> 4, ww = widx & 15;
    int r = tok / WSS, c = tok - r * WSS;
    int h = wh * WSS + r + SHF; if (h >= HH) h -= HH;
    int w = ww * WSS + c + SHF; if (w >= WW2) w -= WW2;
    return (b * HH + h) * WW2 + w;
}

// ---------------------------------------------------------------------------
// LayerNorm (warp per token).  gather==true: read x at shifted-window source.
// ---------------------------------------------------------------------------
__device__ __forceinline__ void ln_body(const float* __restrict__ in,
                                        const float* __restrict__ g,
                                        const float* __restrict__ b,
                                        float* __restrict__ out, bool gather) {
    int m = blockIdx.x * 8 + (threadIdx.x >> 5);
    int lane = threadIdx.x & 31;
    int src = gather ? rowsrc(m) : m;
    const float* xr = in + (size_t)src * CC;
    float v0 = xr[lane], v1 = xr[lane + 32], v2 = xr[lane + 64];
    float s = v0 + v1 + v2;
#pragma unroll
    for (int o = 16; o > 0; o >>= 1) s += __shfl_xor_sync(0xffffffffu, s, o);
    float mean = s * (1.0f / 96.0f);
    float d0 = v0 - mean, d1 = v1 - mean, d2 = v2 - mean;
    float sq = d0 * d0 + d1 * d1 + d2 * d2;
#pragma unroll
    for (int o = 16; o > 0; o >>= 1) sq += __shfl_xor_sync(0xffffffffu, sq, o);
    float rstd = rsqrtf(sq * (1.0f / 96.0f) + 1e-5f);
    float* orow = out + (size_t)m * CC;
    orow[lane]      = d0 * rstd * g[lane]      + b[lane];
    orow[lane + 32] = d1 * rstd * g[lane + 32] + b[lane + 32];
    orow[lane + 64] = d2 * rstd * g[lane + 64] + b[lane + 64];
}

__global__ void __launch_bounds__(256) k_ln1(const float* __restrict__ x,
                                             const float* __restrict__ g,
                                             const float* __restrict__ b) {
    ln_body(x, g, b, g_ln1, true);
}

__global__ void __launch_bounds__(256) k_ln2(const float* __restrict__ g,
                                             const float* __restrict__ b) {
    ln_body(g_x1, g, b, g_ln2, false);
}

// ---------------------------------------------------------------------------
// Combined additive bias:  g_comb[widx][head][i][j] = mask + rel_bias
// ---------------------------------------------------------------------------
__global__ void __launch_bounds__(256) k_comb(const float* __restrict__ mask,
                                              const int* __restrict__ ridx,
                                              const float* __restrict__ table) {
    int wh = blockIdx.x;              // widx*3 + head
    int widx = wh / 3, head = wh - widx * 3;
    const int NN = NTOK * NTOK;
    float* dst = g_comb + (size_t)wh * NN;
    const float* msk = mask + (size_t)widx * NN;
    for (int idx = threadIdx.x; idx < NN; idx += 256)
        dst[idx] = msk[idx] + table[ridx[idx] * NHH + head];
}

// ---------------------------------------------------------------------------
// Generic tiled SGEMM:  C[m][n] = sum_k A[m][k] * W[n][k], 64x64 tile, 4x4/thread
// ---------------------------------------------------------------------------
template <int N, int K, typename Epi>
__device__ __forceinline__ void gemm_body(const float* __restrict__ A,
                                          const float* __restrict__ W,
                                          Epi epi) {
    __shared__ __align__(16) float As[16][68];
    __shared__ __align__(16) float Bs[16][68];
    const int tid = threadIdx.x;
    const int m0 = blockIdx.y * 64;
    const int n0 = blockIdx.x * 64;
    const int lm = tid >> 2;          // 0..63
    const int lk = (tid & 3) << 2;    // 0,4,8,12
    const int ty = tid >> 4;          // 0..15
    const int tx = tid & 15;          // 0..15
    float acc[4][4] = {};

    for (int k0 = 0; k0 < K; k0 += 16) {
        float4 av = *reinterpret_cast<const float4*>(A + (size_t)(m0 + lm) * K + (k0 + lk));
        float4 bv = make_float4(0.f, 0.f, 0.f, 0.f);
        if ((N % 64 == 0) || (n0 + lm < N))
            bv = *reinterpret_cast<const float4*>(W + (size_t)(n0 + lm) * K + (k0 + lk));
        As[lk + 0][lm] = av.x; As[lk + 1][lm] = av.y;
        As[lk + 2][lm] = av.z; As[lk + 3][lm] = av.w;
        Bs[lk + 0][lm] = bv.x; Bs[lk + 1][lm] = bv.y;
        Bs[lk + 2][lm] = bv.z; Bs[lk + 3][lm] = bv.w;
        __syncthreads();
#pragma unroll
        for (int kk = 0; kk < 16; kk++) {
            float4 a = *reinterpret_cast<const float4*>(&As[kk][ty << 2]);
            float4 b = *reinterpret_cast<const float4*>(&Bs[kk][tx << 2]);
            acc[0][0] += a.x * b.x; acc[0][1] += a.x * b.y; acc[0][2] += a.x * b.z; acc[0][3] += a.x * b.w;
            acc[1][0] += a.y * b.x; acc[1][1] += a.y * b.y; acc[1][2] += a.y * b.z; acc[1][3] += a.y * b.w;
            acc[2][0] += a.z * b.x; acc[2][1] += a.z * b.y; acc[2][2] += a.z * b.z; acc[2][3] += a.z * b.w;
            acc[3][0] += a.w * b.x; acc[3][1] += a.w * b.y; acc[3][2] += a.w * b.z; acc[3][3] += a.w * b.w;
        }
        __syncthreads();
    }
#pragma unroll
    for (int i = 0; i < 4; i++)
#pragma unroll
        for (int j = 0; j < 4; j++) {
            int n = n0 + (tx << 2) + j;
            if ((N % 64 == 0) || (n < N))
                epi(m0 + (ty << 2) + i, n, acc[i][j]);
        }
}

// ------------------------- epilogues ---------------------------------------
struct QkvEpi {
    const float* bias;
    __device__ void operator()(int m, int n, float acc) const {
        float val = acc + bias[n];
        int which = n / 96; int rem = n - which * 96;
        int head = rem >> 5; int d = rem & 31;
        int win = m / NTOK; int tok = m - win * NTOK;
        size_t off = ((size_t)(win * 3 + head) * NTOK + tok) * HDD + d;
        if (which == 0)      g_q[off] = val * 0.17677669529663689f;  // HD^-0.5
        else if (which == 1) g_k[off] = val;
        else                 g_v[off] = val;
    }
};

struct ProjEpi {
    const float* x;
    const float* pb;
    __device__ void operator()(int m, int n, float acc) const {
        int src = rowsrc(m);
        size_t o = (size_t)src * CC + n;
        g_x1[o] = x[o] + acc + pb[n];
    }
};

struct Fc1Epi {
    const float* fb;
    __device__ void operator()(int m, int n, float acc) const {
        float v = acc + fb[n];
        // exact GELU: 0.5*v*(1+erf(v/sqrt(2)))
        g_h1[(size_t)m * HIDD + n] = 0.5f * v * (1.0f + erff(v * 0.70710678118654752f));
    }
};

struct Fc2Epi {
    const float* fb;
    float* out;
    __device__ void operator()(int m, int n, float acc) const {
        size_t o = (size_t)m * CC + n;
        out[o] = g_x1[o] + acc + fb[n];
    }
};

// ------------------------- GEMM wrappers -----------------------------------
__global__ void __launch_bounds__(256) k_gemm_qkv(const float* __restrict__ W,
                                                  const float* __restrict__ bias) {
    gemm_body<288, 96>(g_ln1, W, QkvEpi{bias});
}
__global__ void __launch_bounds__(256) k_gemm_proj(const float* __restrict__ W,
                                                   const float* __restrict__ pb,
                                                   const float* __restrict__ x) {
    gemm_body<96, 96>(g_att, W, ProjEpi{x, pb});
}
__global__ void __launch_bounds__(256) k_gemm_fc1(const float* __restrict__ W,
                                                  const float* __restrict__ fb) {
    gemm_body<384, 96>(g_ln2, W, Fc1Epi{fb});
}
__global__ void __launch_bounds__(256) k_gemm_fc2(const float* __restrict__ W,
                                                  const float* __restrict__ fb,
                                                  float* __restrict__ out) {
    gemm_body<96, 384>(g_h1, W, Fc2Epi{fb, out});
}

// ---------------------------------------------------------------------------
// Attention: one block per (window, head), 64 threads (thread i owns row i)
// ---------------------------------------------------------------------------
__global__ void __launch_bounds__(64) k_attn() {
    int bh = blockIdx.x;
    int win = bh / 3, head = bh - win * 3;
    int widx = win & 255;

    __shared__ __align__(16) float Qs[NTOK * 33];
    __shared__ __align__(16) float Ks[NTOK * 32];
    __shared__ __align__(16) float Vs[NTOK * 32];
    __shared__ __align__(16) float Ps[NTOK * 52];
    __shared__ __align__(16) float Cs[NTOK * NTOK];
    __shared__ __align__(16) float Os[NTOK * 33];

    const size_t base = (size_t)bh * (NTOK * HDD);
    const int tid = threadIdx.x;

    for (int idx = tid; idx < NTOK * HDD; idx += 64) {
        int i = idx >> 5, d = idx & 31;
        Qs[i * 33 + d] = g_q[base + idx];
        Ks[idx] = g_k[base + idx];
        Vs[idx] = g_v[base + idx];
    }
    const float* cp = g_comb + (size_t)(widx * 3 + head) * (NTOK * NTOK);
    for (int idx = tid; idx < NTOK * NTOK; idx += 64) Cs[idx] = cp[idx];
    __syncthreads();

    int i = tid;
    if (i < NTOK) {
        float q[32];
#pragma unroll
        for (int d = 0; d < 32; d++) q[d] = Qs[i * 33 + d];

        float mx = -1e30f;
        for (int j = 0; j < NTOK; j++) {
            float s = Cs[i * NTOK + j];
            const float4* kr = reinterpret_cast<const float4*>(Ks + j * 32);
#pragma unroll
            for (int d4 = 0; d4 < 8; d4++) {
                float4 kv = kr[d4];
                s += q[4 * d4] * kv.x + q[4 * d4 + 1] * kv.y
                   + q[4 * d4 + 2] * kv.z + q[4 * d4 + 3] * kv.w;
            }
            Ps[i * 52 + j] = s;
            mx = fmaxf(mx, s);
        }
        float sum = 0.f;
        for (int j = 0; j < NTOK; j++) {
            float e = __expf(Ps[i * 52 + j] - mx);
            Ps[i * 52 + j] = e;
            sum += e;
        }
        float inv = 1.0f / sum;

        float o[32];
#pragma unroll
        for (int d = 0; d < 32; d++) o[d] = 0.f;
        for (int j = 0; j < NTOK; j++) {
            float p = Ps[i * 52 + j];
            const float4* vr = reinterpret_cast<const float4*>(Vs + j * 32);
#pragma unroll
            for (int d4 = 0; d4 < 8; d4++) {
                float4 vv = vr[d4];
                o[4 * d4]     += p * vv.x;
                o[4 * d4 + 1] += p * vv.y;
                o[4 * d4 + 2] += p * vv.z;
                o[4 * d4 + 3] += p * vv.w;
            }
        }
#pragma unroll
        for (int d = 0; d < 32; d++) Os[i * 33 + d] = o[d] * inv;
    }
    __syncthreads();

    float* op = g_att + (size_t)win * (NTOK * CC) + head * HDD;
    for (int idx = tid; idx < NTOK * HDD; idx += 64) {
        int i2 = idx >> 5, d = idx & 31;
        op[i2 * CC + d] = Os[i2 * 33 + d];
    }
}

// ---------------------------------------------------------------------------
// Launch
// ---------------------------------------------------------------------------
extern "C" void kernel_launch(void* const* d_in, const int* in_sizes, int n_in,
                              void* d_out, int out_size) {
    const float* x         = (const float*)d_in[0];
    const float* attn_mask = (const float*)d_in[1];
    const int*   rel_index = (const int*)  d_in[2];
    const float* n1g       = (const float*)d_in[3];
    const float* n1b       = (const float*)d_in[4];
    const float* qkv_w     = (const float*)d_in[5];
    const float* qkv_b     = (const float*)d_in[6];
    const float* proj_w    = (const float*)d_in[7];
    const float* proj_b    = (const float*)d_in[8];
    const float* tbl       = (const float*)d_in[9];
    const float* n2g       = (const float*)d_in[10];
    const float* n2b       = (const float*)d_in[11];
    const float* fc1_w     = (const float*)d_in[12];
    const float* fc1_b     = (const float*)d_in[13];
    const float* fc2_w     = (const float*)d_in[14];
    const float* fc2_b     = (const float*)d_in[15];
    float* out = (float*)d_out;

    k_ln1 <<<MTOK / 8, 256>>>(x, n1g, n1b);
    k_comb<<<256 * NHH, 256>>>(attn_mask, rel_index, tbl);
    k_gemm_qkv <<<dim3(5, MTOK / 64), 256>>>(qkv_w, qkv_b);
    k_attn<<<NWIN * NHH, 64>>>();
    k_gemm_proj<<<dim3(2, MTOK / 64), 256>>>(proj_w, proj_b, x);
    k_ln2 <<<MTOK / 8, 256>>>(n2g, n2b);
    k_gemm_fc1 <<<dim3(6, MTOK / 64), 256>>>(fc1_w, fc1_b);
    k_gemm_fc2 <<<dim3(2, MTOK / 64), 256>>>(fc2_w, fc2_b, out);
}

// round 3
// speedup vs baseline: 1.1589x; 1.1589x over previous
#include <cuda_runtime.h>
#include <cuda_bf16.h>
#include <math.h>
#include <stdint.h>

// ---------------------------------------------------------------------------
// Problem constants
// ---------------------------------------------------------------------------
#define BB    32
#define HH    112
#define WW2   112
#define CC    96
#define NHH   3
#define WSS   7
#define SHF   3
#define HIDD  384
#define NTOK  49              // tokens per window
#define HDD   32              // head dim
#define NWIN  8192            // B * 256 windows
#define MTOK  401408          // NWIN*49 == B*H*W

// ---------------------------------------------------------------------------
// Scratch (device globals; no runtime allocation allowed)
// ---------------------------------------------------------------------------
__device__ __align__(16) float g_ln1[(size_t)MTOK * CC];   // LN1(x), window-token order
__device__ __align__(16) float g_q[(size_t)NWIN * NHH * NTOK * HDD];
__device__ __align__(16) float g_k[(size_t)NWIN * NHH * NTOK * HDD];
__device__ __align__(16) float g_v[(size_t)NWIN * NHH * NTOK * HDD];
__device__ __align__(16) float g_att[(size_t)MTOK * CC];   // attn out (win-token, head*32+d)
__device__ __align__(16) float g_x1[(size_t)MTOK * CC];    // shortcut + proj (original order)
__device__ __align__(16) float g_ln2[(size_t)MTOK * CC];
__device__ __align__(16) float g_h1[(size_t)MTOK * HIDD];  // gelu(fc1)
__device__ __align__(16) float g_comb[(size_t)256 * NHH * NTOK * NTOK]; // mask + rel bias

// window-token index m -> original token row index (b*12544 + h*112 + w)
__device__ __forceinline__ int rowsrc(int m) {
    int win = m / NTOK, tok = m - win * NTOK;
    int b = win >> 8, widx = win & 255;
    int wh = widx >> 4, ww = widx & 15;
    int r = tok / WSS, c = tok - r * WSS;
    int h = wh * WSS + r + SHF; if (h >= HH) h -= HH;
    int w = ww * WSS + c + SHF; if (w >= WW2) w -= WW2;
    return (b * HH + h) * WW2 + w;
}

// ---------------------------------------------------------------------------
// LayerNorm (warp per token).  gather==true: read x at shifted-window source.
// ---------------------------------------------------------------------------
__device__ __forceinline__ void ln_body(const float* __restrict__ in,
                                        const float* __restrict__ g,
                                        const float* __restrict__ b,
                                        float* __restrict__ out, bool gather) {
    int m = blockIdx.x * 8 + (threadIdx.x >> 5);
    int lane = threadIdx.x & 31;
    int src = gather ? rowsrc(m) : m;
    const float* xr = in + (size_t)src * CC;
    float v0 = xr[lane], v1 = xr[lane + 32], v2 = xr[lane + 64];
    float s = v0 + v1 + v2;
#pragma unroll
    for (int o = 16; o > 0; o >>= 1) s += __shfl_xor_sync(0xffffffffu, s, o);
    float mean = s * (1.0f / 96.0f);
    float d0 = v0 - mean, d1 = v1 - mean, d2 = v2 - mean;
    float sq = d0 * d0 + d1 * d1 + d2 * d2;
#pragma unroll
    for (int o = 16; o > 0; o >>= 1) sq += __shfl_xor_sync(0xffffffffu, sq, o);
    float rstd = rsqrtf(sq * (1.0f / 96.0f) + 1e-5f);
    float* orow = out + (size_t)m * CC;
    orow[lane]      = d0 * rstd * g[lane]      + b[lane];
    orow[lane + 32] = d1 * rstd * g[lane + 32] + b[lane + 32];
    orow[lane + 64] = d2 * rstd * g[lane + 64] + b[lane + 64];
}

__global__ void __launch_bounds__(256) k_ln1(const float* __restrict__ x,
                                             const float* __restrict__ g,
                                             const float* __restrict__ b) {
    ln_body(x, g, b, g_ln1, true);
}

__global__ void __launch_bounds__(256) k_ln2(const float* __restrict__ g,
                                             const float* __restrict__ b) {
    ln_body(g_x1, g, b, g_ln2, false);
}

// ---------------------------------------------------------------------------
// Combined additive bias:  g_comb[widx][head][i][j] = mask + rel_bias
// ---------------------------------------------------------------------------
__global__ void __launch_bounds__(256) k_comb(const float* __restrict__ mask,
                                              const int* __restrict__ ridx,
                                              const float* __restrict__ table) {
    int wh = blockIdx.x;              // widx*3 + head
    int widx = wh / 3, head = wh - widx * 3;
    const int NN = NTOK * NTOK;
    float* dst = g_comb + (size_t)wh * NN;
    const float* msk = mask + (size_t)widx * NN;
    for (int idx = threadIdx.x; idx < NN; idx += 256)
        dst[idx] = msk[idx] + table[ridx[idx] * NHH + head];
}

// ---------------------------------------------------------------------------
// TF32 tensor-core GEMM:  C[m][n] = sum_k A[m][k] * W[n][k]
// 128x64 tile, BK=32, 256 threads = 8 warps (4x2), warp tile 32x32 (2x4 mma)
// ---------------------------------------------------------------------------
__device__ __forceinline__ uint32_t f2tf(float x) {
    uint32_t r;
    asm("cvt.rna.tf32.f32 %0, %1;" : "=r"(r) : "f"(x));
    return r;
}

__device__ __forceinline__ void mma_tf32(float* c, const uint32_t* a, const uint32_t* b) {
    asm volatile(
        "mma.sync.aligned.m16n8k8.row.col.f32.tf32.tf32.f32 "
        "{%0,%1,%2,%3}, {%4,%5,%6,%7}, {%8,%9}, {%0,%1,%2,%3};"
        : "+f"(c[0]), "+f"(c[1]), "+f"(c[2]), "+f"(c[3])
        : "r"(a[0]), "r"(a[1]), "r"(a[2]), "r"(a[3]), "r"(b[0]), "r"(b[1]));
}

template <int N, int K, typename Epi>
__device__ __forceinline__ void gemm_body(const float* __restrict__ A,
                                          const float* __restrict__ W,
                                          Epi epi) {
    __shared__ __align__(16) uint32_t As[128][36];
    __shared__ __align__(16) uint32_t Bs[64][36];
    const int tid = threadIdx.x;
    const int wid = tid >> 5, lane = tid & 31;
    const int warp_m = wid >> 1, warp_n = wid & 1;
    const int grp = lane >> 2, qid = lane & 3;
    const int m0 = blockIdx.y * 128;
    const int n0 = blockIdx.x * 64;

    float c[2][4][4];
#pragma unroll
    for (int i = 0; i < 2; i++)
#pragma unroll
        for (int j = 0; j < 4; j++)
#pragma unroll
            for (int e = 0; e < 4; e++) c[i][j][e] = 0.f;

    for (int k0 = 0; k0 < K; k0 += 32) {
        // ---- load A tile: 128 rows x 32 cols = 1024 float4 ----
#pragma unroll
        for (int i = 0; i < 4; i++) {
            int idx = tid + i * 256;
            int row = idx >> 3, col = (idx & 7) << 2;
            float4 v = *reinterpret_cast<const float4*>(A + (size_t)(m0 + row) * K + k0 + col);
            As[row][col + 0] = f2tf(v.x); As[row][col + 1] = f2tf(v.y);
            As[row][col + 2] = f2tf(v.z); As[row][col + 3] = f2tf(v.w);
        }
        // ---- load B tile: 64 rows x 32 cols = 512 float4 ----
#pragma unroll
        for (int i = 0; i < 2; i++) {
            int idx = tid + i * 256;
            int row = idx >> 3, col = (idx & 7) << 2;
            float4 v = make_float4(0.f, 0.f, 0.f, 0.f);
            if ((N % 64 == 0) || (n0 + row < N))
                v = *reinterpret_cast<const float4*>(W + (size_t)(n0 + row) * K + k0 + col);
            Bs[row][col + 0] = f2tf(v.x); Bs[row][col + 1] = f2tf(v.y);
            Bs[row][col + 2] = f2tf(v.z); Bs[row][col + 3] = f2tf(v.w);
        }
        __syncthreads();

#pragma unroll
        for (int kk = 0; kk < 32; kk += 8) {
            uint32_t a[2][4], b[4][2];
#pragma unroll
            for (int i = 0; i < 2; i++) {
                int ar = warp_m * 32 + i * 16 + grp;
                a[i][0] = As[ar][kk + qid];
                a[i][1] = As[ar + 8][kk + qid];
                a[i][2] = As[ar][kk + qid + 4];
                a[i][3] = As[ar + 8][kk + qid + 4];
            }
#pragma unroll
            for (int j = 0; j < 4; j++) {
                int br = warp_n * 32 + j * 8 + grp;
                b[j][0] = Bs[br][kk + qid];
                b[j][1] = Bs[br][kk + qid + 4];
            }
#pragma unroll
            for (int i = 0; i < 2; i++)
#pragma unroll
                for (int j = 0; j < 4; j++)
                    mma_tf32(c[i][j], a[i], b[j]);
        }
        __syncthreads();
    }

    // ---- epilogue ----
#pragma unroll
    for (int i = 0; i < 2; i++) {
        int r0 = m0 + warp_m * 32 + i * 16 + grp;
#pragma unroll
        for (int j = 0; j < 4; j++) {
            int cn = n0 + warp_n * 32 + j * 8 + qid * 2;
            if ((N % 64 == 0) || (cn < N)) {
                epi(r0, cn, c[i][j][0]);
                epi(r0 + 8, cn, c[i][j][2]);
            }
            if ((N % 64 == 0) || (cn + 1 < N)) {
                epi(r0, cn + 1, c[i][j][1]);
                epi(r0 + 8, cn + 1, c[i][j][3]);
            }
        }
    }
}

// ------------------------- epilogues ---------------------------------------
struct QkvEpi {
    const float* bias;
    __device__ void operator()(int m, int n, float acc) const {
        float val = acc + bias[n];
        int which = n / 96; int rem = n - which * 96;
        int head = rem >> 5; int d = rem & 31;
        int win = m / NTOK; int tok = m - win * NTOK;
        size_t off = ((size_t)(win * 3 + head) * NTOK + tok) * HDD + d;
        if (which == 0)      g_q[off] = val * 0.17677669529663689f;  // HD^-0.5
        else if (which == 1) g_k[off] = val;
        else                 g_v[off] = val;
    }
};

struct ProjEpi {
    const float* x;
    const float* pb;
    __device__ void operator()(int m, int n, float acc) const {
        int src = rowsrc(m);
        size_t o = (size_t)src * CC + n;
        g_x1[o] = x[o] + acc + pb[n];
    }
};

struct Fc1Epi {
    const float* fb;
    __device__ void operator()(int m, int n, float acc) const {
        float v = acc + fb[n];
        // exact GELU: 0.5*v*(1+erf(v/sqrt(2)))
        g_h1[(size_t)m * HIDD + n] = 0.5f * v * (1.0f + erff(v * 0.70710678118654752f));
    }
};

struct Fc2Epi {
    const float* fb;
    float* out;
    __device__ void operator()(int m, int n, float acc) const {
        size_t o = (size_t)m * CC + n;
        out[o] = g_x1[o] + acc + fb[n];
    }
};

// ------------------------- GEMM wrappers -----------------------------------
__global__ void __launch_bounds__(256) k_gemm_qkv(const float* __restrict__ W,
                                                  const float* __restrict__ bias) {
    gemm_body<288, 96>(g_ln1, W, QkvEpi{bias});
}
__global__ void __launch_bounds__(256) k_gemm_proj(const float* __restrict__ W,
                                                   const float* __restrict__ pb,
                                                   const float* __restrict__ x) {
    gemm_body<96, 96>(g_att, W, ProjEpi{x, pb});
}
__global__ void __launch_bounds__(256) k_gemm_fc1(const float* __restrict__ W,
                                                  const float* __restrict__ fb) {
    gemm_body<384, 96>(g_ln2, W, Fc1Epi{fb});
}
__global__ void __launch_bounds__(256) k_gemm_fc2(const float* __restrict__ W,
                                                  const float* __restrict__ fb,
                                                  float* __restrict__ out) {
    gemm_body<96, 384>(g_h1, W, Fc2Epi{fb, out});
}

// ---------------------------------------------------------------------------
// Attention: one block per (window, head), 64 threads (thread i owns row i)
// ---------------------------------------------------------------------------
__global__ void __launch_bounds__(64) k_attn() {
    int bh = blockIdx.x;
    int win = bh / 3, head = bh - win * 3;
    int widx = win & 255;

    __shared__ __align__(16) float Qs[NTOK * 33];
    __shared__ __align__(16) float Ks[NTOK * 32];
    __shared__ __align__(16) float Vs[NTOK * 32];
    __shared__ __align__(16) float Ps[NTOK * 52];
    __shared__ __align__(16) float Cs[NTOK * NTOK];
    __shared__ __align__(16) float Os[NTOK * 33];

    const size_t base = (size_t)bh * (NTOK * HDD);
    const int tid = threadIdx.x;

    for (int idx = tid; idx < NTOK * HDD; idx += 64) {
        int i = idx >> 5, d = idx & 31;
        Qs[i * 33 + d] = g_q[base + idx];
        Ks[idx] = g_k[base + idx];
        Vs[idx] = g_v[base + idx];
    }
    const float* cp = g_comb + (size_t)(widx * 3 + head) * (NTOK * NTOK);
    for (int idx = tid; idx < NTOK * NTOK; idx += 64) Cs[idx] = cp[idx];
    __syncthreads();

    int i = tid;
    if (i < NTOK) {
        float q[32];
#pragma unroll
        for (int d = 0; d < 32; d++) q[d] = Qs[i * 33 + d];

        float mx = -1e30f;
        for (int j = 0; j < NTOK; j++) {
            float s = Cs[i * NTOK + j];
            const float4* kr = reinterpret_cast<const float4*>(Ks + j * 32);
#pragma unroll
            for (int d4 = 0; d4 < 8; d4++) {
                float4 kv = kr[d4];
                s += q[4 * d4] * kv.x + q[4 * d4 + 1] * kv.y
                   + q[4 * d4 + 2] * kv.z + q[4 * d4 + 3] * kv.w;
            }
            Ps[i * 52 + j] = s;
            mx = fmaxf(mx, s);
        }
        float sum = 0.f;
        for (int j = 0; j < NTOK; j++) {
            float e = __expf(Ps[i * 52 + j] - mx);
            Ps[i * 52 + j] = e;
            sum += e;
        }
        float inv = 1.0f / sum;

        float o[32];
#pragma unroll
        for (int d = 0; d < 32; d++) o[d] = 0.f;
        for (int j = 0; j < NTOK; j++) {
            float p = Ps[i * 52 + j];
            const float4* vr = reinterpret_cast<const float4*>(Vs + j * 32);
#pragma unroll
            for (int d4 = 0; d4 < 8; d4++) {
                float4 vv = vr[d4];
                o[4 * d4]     += p * vv.x;
                o[4 * d4 + 1] += p * vv.y;
                o[4 * d4 + 2] += p * vv.z;
                o[4 * d4 + 3] += p * vv.w;
            }
        }
#pragma unroll
        for (int d = 0; d < 32; d++) Os[i * 33 + d] = o[d] * inv;
    }
    __syncthreads();

    float* op = g_att + (size_t)win * (NTOK * CC) + head * HDD;
    for (int idx = tid; idx < NTOK * HDD; idx += 64) {
        int i2 = idx >> 5, d = idx & 31;
        op[i2 * CC + d] = Os[i2 * 33 + d];
    }
}

// ---------------------------------------------------------------------------
// Launch
// ---------------------------------------------------------------------------
extern "C" void kernel_launch(void* const* d_in, const int* in_sizes, int n_in,
                              void* d_out, int out_size) {
    const float* x         = (const float*)d_in[0];
    const float* attn_mask = (const float*)d_in[1];
    const int*   rel_index = (const int*)  d_in[2];
    const float* n1g       = (const float*)d_in[3];
    const float* n1b       = (const float*)d_in[4];
    const float* qkv_w     = (const float*)d_in[5];
    const float* qkv_b     = (const float*)d_in[6];
    const float* proj_w    = (const float*)d_in[7];
    const float* proj_b    = (const float*)d_in[8];
    const float* tbl       = (const float*)d_in[9];
    const float* n2g       = (const float*)d_in[10];
    const float* n2b       = (const float*)d_in[11];
    const float* fc1_w     = (const float*)d_in[12];
    const float* fc1_b     = (const float*)d_in[13];
    const float* fc2_w     = (const float*)d_in[14];
    const float* fc2_b     = (const float*)d_in[15];
    float* out = (float*)d_out;

    k_ln1 <<<MTOK / 8, 256>>>(x, n1g, n1b);
    k_comb<<<256 * NHH, 256>>>(attn_mask, rel_index, tbl);
    k_gemm_qkv <<<dim3(5, MTOK / 128), 256>>>(qkv_w, qkv_b);
    k_attn<<<NWIN * NHH, 64>>>();
    k_gemm_proj<<<dim3(2, MTOK / 128), 256>>>(proj_w, proj_b, x);
    k_ln2 <<<MTOK / 8, 256>>>(n2g, n2b);
    k_gemm_fc1 <<<dim3(6, MTOK / 128), 256>>>(fc1_w, fc1_b);
    k_gemm_fc2 <<<dim3(2, MTOK / 128), 256>>>(fc2_w, fc2_b, out);
}

// round 4
// speedup vs baseline: 2.1710x; 1.8734x over previous
#include <cuda_runtime.h>
#include <cuda_bf16.h>
#include <math.h>
#include <stdint.h>

// ---------------------------------------------------------------------------
// Problem constants
// ---------------------------------------------------------------------------
#define BB    32
#define HH    112
#define WW2   112
#define CC    96
#define NHH   3
#define WSS   7
#define SHF   3
#define HIDD  384
#define NTOK  49              // tokens per window
#define HDD   32              // head dim
#define NWIN  8192            // B * 256 windows
#define MTOK  401408          // NWIN*49 == B*H*W

// ---------------------------------------------------------------------------
// Scratch (device globals; no runtime allocation allowed)
// ---------------------------------------------------------------------------
__device__ __align__(16) float g_ln1[(size_t)MTOK * CC];   // LN1(x), window-token order
__device__ __align__(16) float g_q[(size_t)NWIN * NHH * NTOK * HDD];
__device__ __align__(16) float g_k[(size_t)NWIN * NHH * NTOK * HDD];
__device__ __align__(16) float g_v[(size_t)NWIN * NHH * NTOK * HDD];
__device__ __align__(16) float g_att[(size_t)MTOK * CC];   // attn out (win-token, head*32+d)
__device__ __align__(16) float g_x1[(size_t)MTOK * CC];    // shortcut + proj (original order)
__device__ __align__(16) float g_ln2[(size_t)MTOK * CC];
__device__ __align__(16) float g_h1[(size_t)MTOK * HIDD];  // gelu(fc1)
__device__ __align__(16) float g_comb[(size_t)256 * NHH * NTOK * NTOK]; // mask + rel bias

// window-token index m -> original token row index (b*12544 + h*112 + w)
__device__ __forceinline__ int rowsrc(int m) {
    int win = m / NTOK, tok = m - win * NTOK;
    int b = win >> 8, widx = win & 255;
    int wh = widx >> 4, ww = widx & 15;
    int r = tok / WSS, c = tok - r * WSS;
    int h = wh * WSS + r + SHF; if (h >= HH) h -= HH;
    int w = ww * WSS + c + SHF; if (w >= WW2) w -= WW2;
    return (b * HH + h) * WW2 + w;
}

// ---------------------------------------------------------------------------
// LayerNorm (warp per token).  gather==true: read x at shifted-window source.
// ---------------------------------------------------------------------------
__device__ __forceinline__ void ln_body(const float* __restrict__ in,
                                        const float* __restrict__ g,
                                        const float* __restrict__ b,
                                        float* __restrict__ out, bool gather) {
    int m = blockIdx.x * 8 + (threadIdx.x >> 5);
    int lane = threadIdx.x & 31;
    int src = gather ? rowsrc(m) : m;
    const float* xr = in + (size_t)src * CC;
    float v0 = xr[lane], v1 = xr[lane + 32], v2 = xr[lane + 64];
    float s = v0 + v1 + v2;
#pragma unroll
    for (int o = 16; o > 0; o >>= 1) s += __shfl_xor_sync(0xffffffffu, s, o);
    float mean = s * (1.0f / 96.0f);
    float d0 = v0 - mean, d1 = v1 - mean, d2 = v2 - mean;
    float sq = d0 * d0 + d1 * d1 + d2 * d2;
#pragma unroll
    for (int o = 16; o > 0; o >>= 1) sq += __shfl_xor_sync(0xffffffffu, sq, o);
    float rstd = rsqrtf(sq * (1.0f / 96.0f) + 1e-5f);
    float* orow = out + (size_t)m * CC;
    orow[lane]      = d0 * rstd * g[lane]      + b[lane];
    orow[lane + 32] = d1 * rstd * g[lane + 32] + b[lane + 32];
    orow[lane + 64] = d2 * rstd * g[lane + 64] + b[lane + 64];
}

__global__ void __launch_bounds__(256) k_ln1(const float* __restrict__ x,
                                             const float* __restrict__ g,
                                             const float* __restrict__ b) {
    ln_body(x, g, b, g_ln1, true);
}

__global__ void __launch_bounds__(256) k_ln2(const float* __restrict__ g,
                                             const float* __restrict__ b) {
    ln_body(g_x1, g, b, g_ln2, false);
}

// ---------------------------------------------------------------------------
// Combined additive bias:  g_comb[widx][head][i][j] = mask + rel_bias
// ---------------------------------------------------------------------------
__global__ void __launch_bounds__(256) k_comb(const float* __restrict__ mask,
                                              const int* __restrict__ ridx,
                                              const float* __restrict__ table) {
    int wh = blockIdx.x;              // widx*3 + head
    int widx = wh / 3, head = wh - widx * 3;
    const int NN = NTOK * NTOK;
    float* dst = g_comb + (size_t)wh * NN;
    const float* msk = mask + (size_t)widx * NN;
    for (int idx = threadIdx.x; idx < NN; idx += 256)
        dst[idx] = msk[idx] + table[ridx[idx] * NHH + head];
}

// ---------------------------------------------------------------------------
// BF16 tensor-core GEMM:  C[m][n] = sum_k A[m][k] * W[n][k]
// 128x64 tile, BK=96 (whole-K for K=96), 8 warps (4x2), warp tile 32x32
// smem holds bf16 pairs (uint32), row stride 52 pairs -> conflict-free frags
// ---------------------------------------------------------------------------
__device__ __forceinline__ uint32_t packbf(float x, float y) {
    __nv_bfloat162 h = __floats2bfloat162_rn(x, y);
    return *reinterpret_cast<uint32_t*>(&h);
}

__device__ __forceinline__ void mma_bf16(float* c, const uint32_t* a, const uint32_t* b) {
    asm volatile(
        "mma.sync.aligned.m16n8k16.row.col.f32.bf16.bf16.f32 "
        "{%0,%1,%2,%3}, {%4,%5,%6,%7}, {%8,%9}, {%0,%1,%2,%3};"
        : "+f"(c[0]), "+f"(c[1]), "+f"(c[2]), "+f"(c[3])
        : "r"(a[0]), "r"(a[1]), "r"(a[2]), "r"(a[3]), "r"(b[0]), "r"(b[1]));
}

template <int N, int K, typename Epi>
__device__ __forceinline__ void gemm_body(const float* __restrict__ A,
                                          const float* __restrict__ W,
                                          Epi epi) {
    constexpr int BK = 96;            // K % 96 == 0 for all four GEMMs
    constexpr int KP = BK / 2;        // 48 bf16x2 pairs
    constexpr int ST = KP + 4;        // 52: conflict-free fragment stride
    __shared__ __align__(16) uint32_t As[128][ST];
    __shared__ __align__(16) uint32_t Bs[64][ST];
    const int tid = threadIdx.x;
    const int wid = tid >> 5, lane = tid & 31;
    const int warp_m = wid >> 1, warp_n = wid & 1;
    const int grp = lane >> 2, qid = lane & 3;
    const int m0 = blockIdx.y * 128;
    const int n0 = blockIdx.x * 64;

    float c[2][4][4];
#pragma unroll
    for (int i = 0; i < 2; i++)
#pragma unroll
        for (int j = 0; j < 4; j++)
#pragma unroll
            for (int e = 0; e < 4; e++) c[i][j][e] = 0.f;

    for (int k0 = 0; k0 < K; k0 += BK) {
        // ---- A tile: 128 rows x 24 float4 = 3072 loads / 256 thr = 12 ----
#pragma unroll
        for (int i = 0; i < 12; i++) {
            int idx = tid + i * 256;
            int row = idx / 24, c4 = idx - row * 24;
            float4 v = *reinterpret_cast<const float4*>(A + (size_t)(m0 + row) * K + k0 + c4 * 4);
            As[row][c4 * 2]     = packbf(v.x, v.y);
            As[row][c4 * 2 + 1] = packbf(v.z, v.w);
        }
        // ---- B tile: 64 rows x 24 float4 = 1536 / 256 = 6 ----
#pragma unroll
        for (int i = 0; i < 6; i++) {
            int idx = tid + i * 256;
            int row = idx / 24, c4 = idx - row * 24;
            float4 v = make_float4(0.f, 0.f, 0.f, 0.f);
            if ((N % 64 == 0) || (n0 + row < N))
                v = *reinterpret_cast<const float4*>(W + (size_t)(n0 + row) * K + k0 + c4 * 4);
            Bs[row][c4 * 2]     = packbf(v.x, v.y);
            Bs[row][c4 * 2 + 1] = packbf(v.z, v.w);
        }
        __syncthreads();

#pragma unroll
        for (int kk = 0; kk < KP; kk += 8) {   // 6 k16 steps
            uint32_t a[2][4], b[4][2];
#pragma unroll
            for (int i = 0; i < 2; i++) {
                int ar = warp_m * 32 + i * 16 + grp;
                a[i][0] = As[ar][kk + qid];
                a[i][1] = As[ar + 8][kk + qid];
                a[i][2] = As[ar][kk + qid + 4];
                a[i][3] = As[ar + 8][kk + qid + 4];
            }
#pragma unroll
            for (int j = 0; j < 4; j++) {
                int br = warp_n * 32 + j * 8 + grp;
                b[j][0] = Bs[br][kk + qid];
                b[j][1] = Bs[br][kk + qid + 4];
            }
#pragma unroll
            for (int i = 0; i < 2; i++)
#pragma unroll
                for (int j = 0; j < 4; j++)
                    mma_bf16(c[i][j], a[i], b[j]);
        }
        __syncthreads();
    }

    // ---- epilogue ----
#pragma unroll
    for (int i = 0; i < 2; i++) {
        int r0 = m0 + warp_m * 32 + i * 16 + grp;
#pragma unroll
        for (int j = 0; j < 4; j++) {
            int cn = n0 + warp_n * 32 + j * 8 + qid * 2;
            if ((N % 64 == 0) || (cn < N)) {
                epi(r0, cn, c[i][j][0]);
                epi(r0 + 8, cn, c[i][j][2]);
            }
            if ((N % 64 == 0) || (cn + 1 < N)) {
                epi(r0, cn + 1, c[i][j][1]);
                epi(r0 + 8, cn + 1, c[i][j][3]);
            }
        }
    }
}

// ------------------------- epilogues ---------------------------------------
struct QkvEpi {
    const float* bias;
    __device__ void operator()(int m, int n, float acc) const {
        float val = acc + bias[n];
        int which = n / 96; int rem = n - which * 96;
        int head = rem >> 5; int d = rem & 31;
        int win = m / NTOK; int tok = m - win * NTOK;
        size_t off = ((size_t)(win * 3 + head) * NTOK + tok) * HDD + d;
        if (which == 0)      g_q[off] = val * 0.17677669529663689f;  // HD^-0.5
        else if (which == 1) g_k[off] = val;
        else                 g_v[off] = val;
    }
};

struct ProjEpi {
    const float* x;
    const float* pb;
    __device__ void operator()(int m, int n, float acc) const {
        int src = rowsrc(m);
        size_t o = (size_t)src * CC + n;
        g_x1[o] = x[o] + acc + pb[n];
    }
};

struct Fc1Epi {
    const float* fb;
    __device__ void operator()(int m, int n, float acc) const {
        float v = acc + fb[n];
        // exact GELU: 0.5*v*(1+erf(v/sqrt(2)))
        g_h1[(size_t)m * HIDD + n] = 0.5f * v * (1.0f + erff(v * 0.70710678118654752f));
    }
};

struct Fc2Epi {
    const float* fb;
    float* out;
    __device__ void operator()(int m, int n, float acc) const {
        size_t o = (size_t)m * CC + n;
        out[o] = g_x1[o] + acc + fb[n];
    }
};

// ------------------------- GEMM wrappers -----------------------------------
__global__ void __launch_bounds__(256) k_gemm_qkv(const float* __restrict__ W,
                                                  const float* __restrict__ bias) {
    gemm_body<288, 96>(g_ln1, W, QkvEpi{bias});
}
__global__ void __launch_bounds__(256) k_gemm_proj(const float* __restrict__ W,
                                                   const float* __restrict__ pb,
                                                   const float* __restrict__ x) {
    gemm_body<96, 96>(g_att, W, ProjEpi{x, pb});
}
__global__ void __launch_bounds__(256) k_gemm_fc1(const float* __restrict__ W,
                                                  const float* __restrict__ fb) {
    gemm_body<384, 96>(g_ln2, W, Fc1Epi{fb});
}
__global__ void __launch_bounds__(256) k_gemm_fc2(const float* __restrict__ W,
                                                  const float* __restrict__ fb,
                                                  float* __restrict__ out) {
    gemm_body<96, 384>(g_h1, W, Fc2Epi{fb, out});
}

// ---------------------------------------------------------------------------
// Attention: one block per (window, head), 64 threads (thread i owns row i)
// smem diet: comb folded into Ps, Q staged through Os -> ~29KB/block
// ---------------------------------------------------------------------------
__global__ void __launch_bounds__(64) k_attn() {
    int bh = blockIdx.x;
    int win = bh / 3, head = bh - win * 3;
    int widx = win & 255;

    __shared__ __align__(16) float Ks[NTOK * 32];
    __shared__ __align__(16) float Vs[NTOK * 32];
    __shared__ __align__(16) float Ps[NTOK * 51];   // scores; stride 51 conflict-free
    __shared__ __align__(16) float Os[NTOK * 33];   // Q staging, then output staging

    const size_t base = (size_t)bh * (NTOK * HDD);
    const int tid = threadIdx.x;

    for (int idx = tid; idx < NTOK * HDD; idx += 64) {
        int i = idx >> 5, d = idx & 31;
        Os[i * 33 + d] = g_q[base + idx];           // Q staged into Os
        Ks[idx] = g_k[base + idx];
        Vs[idx] = g_v[base + idx];
    }
    // comb folded directly into score buffer (coalesced gmem read)
    const float* cp = g_comb + (size_t)(widx * 3 + head) * (NTOK * NTOK);
    for (int idx = tid; idx < NTOK * NTOK; idx += 64) {
        int i = idx / NTOK, j = idx - i * NTOK;
        Ps[i * 51 + j] = cp[idx];
    }
    __syncthreads();

    int i = tid;
    if (i < NTOK) {
        float q[32];
#pragma unroll
        for (int d = 0; d < 32; d++) q[d] = Os[i * 33 + d];

        float mx = -1e30f;
        for (int j = 0; j < NTOK; j++) {
            float s = Ps[i * 51 + j];
            const float4* kr = reinterpret_cast<const float4*>(Ks + j * 32);
#pragma unroll
            for (int d4 = 0; d4 < 8; d4++) {
                float4 kv = kr[d4];
                s += q[4 * d4] * kv.x + q[4 * d4 + 1] * kv.y
                   + q[4 * d4 + 2] * kv.z + q[4 * d4 + 3] * kv.w;
            }
            Ps[i * 51 + j] = s;
            mx = fmaxf(mx, s);
        }
        float sum = 0.f;
        for (int j = 0; j < NTOK; j++) {
            float e = __expf(Ps[i * 51 + j] - mx);
            Ps[i * 51 + j] = e;
            sum += e;
        }
        float inv = 1.0f / sum;

        float o[32];
#pragma unroll
        for (int d = 0; d < 32; d++) o[d] = 0.f;
        for (int j = 0; j < NTOK; j++) {
            float p = Ps[i * 51 + j];
            const float4* vr = reinterpret_cast<const float4*>(Vs + j * 32);
#pragma unroll
            for (int d4 = 0; d4 < 8; d4++) {
                float4 vv = vr[d4];
                o[4 * d4]     += p * vv.x;
                o[4 * d4 + 1] += p * vv.y;
                o[4 * d4 + 2] += p * vv.z;
                o[4 * d4 + 3] += p * vv.w;
            }
        }
#pragma unroll
        for (int d = 0; d < 32; d++) Os[i * 33 + d] = o[d] * inv;  // own row: no race
    }
    __syncthreads();

    float* op = g_att + (size_t)win * (NTOK * CC) + head * HDD;
    for (int idx = tid; idx < NTOK * HDD; idx += 64) {
        int i2 = idx >> 5, d = idx & 31;
        op[i2 * CC + d] = Os[i2 * 33 + d];
    }
}

// ---------------------------------------------------------------------------
// Launch
// ---------------------------------------------------------------------------
extern "C" void kernel_launch(void* const* d_in, const int* in_sizes, int n_in,
                              void* d_out, int out_size) {
    const float* x         = (const float*)d_in[0];
    const float* attn_mask = (const float*)d_in[1];
    const int*   rel_index = (const int*)  d_in[2];
    const float* n1g       = (const float*)d_in[3];
    const float* n1b       = (const float*)d_in[4];
    const float* qkv_w     = (const float*)d_in[5];
    const float* qkv_b     = (const float*)d_in[6];
    const float* proj_w    = (const float*)d_in[7];
    const float* proj_b    = (const float*)d_in[8];
    const float* tbl       = (const float*)d_in[9];
    const float* n2g       = (const float*)d_in[10];
    const float* n2b       = (const float*)d_in[11];
    const float* fc1_w     = (const float*)d_in[12];
    const float* fc1_b     = (const float*)d_in[13];
    const float* fc2_w     = (const float*)d_in[14];
    const float* fc2_b     = (const float*)d_in[15];
    float* out = (float*)d_out;

    k_ln1 <<<MTOK / 8, 256>>>(x, n1g, n1b);
    k_comb<<<256 * NHH, 256>>>(attn_mask, rel_index, tbl);
    k_gemm_qkv <<<dim3(5, MTOK / 128), 256>>>(qkv_w, qkv_b);
    k_attn<<<NWIN * NHH, 64>>>();
    k_gemm_proj<<<dim3(2, MTOK / 128), 256>>>(proj_w, proj_b, x);
    k_ln2 <<<MTOK / 8, 256>>>(n2g, n2b);
    k_gemm_fc1 <<<dim3(6, MTOK / 128), 256>>>(fc1_w, fc1_b);
    k_gemm_fc2 <<<dim3(2, MTOK / 128), 256>>>(fc2_w, fc2_b, out);
}

// round 5
// speedup vs baseline: 2.9732x; 1.3695x over previous
#include <cuda_runtime.h>
#include <cuda_bf16.h>
#include <math.h>
#include <stdint.h>

// ---------------------------------------------------------------------------
// Problem constants
// ---------------------------------------------------------------------------
#define BB    32
#define HH    112
#define WW2   112
#define CC    96
#define NHH   3
#define WSS   7
#define SHF   3
#define HIDD  384
#define NTOK  49
#define HDD   32
#define NWIN  8192
#define MTOK  401408

typedef __nv_bfloat16 bf16;
typedef __nv_bfloat162 bf162;

// ---------------------------------------------------------------------------
// Scratch (device globals)
// ---------------------------------------------------------------------------
__device__ __align__(16) bf16  g_ln1h[(size_t)MTOK * CC];
__device__ __align__(16) bf16  g_qh[(size_t)NWIN * NHH * NTOK * HDD];
__device__ __align__(16) bf16  g_kh[(size_t)NWIN * NHH * NTOK * HDD];
__device__ __align__(16) bf16  g_vh[(size_t)NWIN * NHH * NTOK * HDD];
__device__ __align__(16) bf16  g_atth[(size_t)MTOK * CC];
__device__ __align__(16) float g_x1[(size_t)MTOK * CC];
__device__ __align__(16) bf16  g_ln2h[(size_t)MTOK * CC];
__device__ __align__(16) bf16  g_h1h[(size_t)MTOK * HIDD];
__device__ __align__(16) float g_comb[(size_t)256 * NHH * NTOK * NTOK];
// bf16 weights
__device__ __align__(16) bf16 g_wqkv[288 * 96];
__device__ __align__(16) bf16 g_wproj[96 * 96];
__device__ __align__(16) bf16 g_wfc1[384 * 96];
__device__ __align__(16) bf16 g_wfc2[96 * 384];

__device__ __forceinline__ int rowsrc(int m) {
    int win = m / NTOK, tok = m - win * NTOK;
    int b = win >> 8, widx = win & 255;
    int wh = widx >> 4, ww = widx & 15;
    int r = tok / WSS, c = tok - r * WSS;
    int h = wh * WSS + r + SHF; if (h >= HH) h -= HH;
    int w = ww * WSS + c + SHF; if (w >= WW2) w -= WW2;
    return (b * HH + h) * WW2 + w;
}

// ---------------------------------------------------------------------------
// Weight conversion (runs every launch; tiny)
// ---------------------------------------------------------------------------
__global__ void __launch_bounds__(256) k_prep(const float* __restrict__ qkvw,
                                              const float* __restrict__ projw,
                                              const float* __restrict__ fc1w,
                                              const float* __restrict__ fc2w) {
    int i = blockIdx.x * 256 + threadIdx.x;
    if (i < 27648)               g_wqkv[i]           = __float2bfloat16(qkvw[i]);
    else if (i < 27648 + 9216)   g_wproj[i - 27648]  = __float2bfloat16(projw[i - 27648]);
    else if (i < 36864 + 36864)  g_wfc1[i - 36864]   = __float2bfloat16(fc1w[i - 36864]);
    else if (i < 110592)         g_wfc2[i - 73728]   = __float2bfloat16(fc2w[i - 73728]);
}

// ---------------------------------------------------------------------------
// LayerNorm (warp per token)
// ---------------------------------------------------------------------------
template <typename OutT>
__device__ __forceinline__ void ln_body(const float* __restrict__ in,
                                        const float* __restrict__ g,
                                        const float* __restrict__ b,
                                        OutT* __restrict__ out, bool gather) {
    int m = blockIdx.x * 8 + (threadIdx.x >> 5);
    int lane = threadIdx.x & 31;
    int src = gather ? rowsrc(m) : m;
    const float* xr = in + (size_t)src * CC;
    float v0 = xr[lane], v1 = xr[lane + 32], v2 = xr[lane + 64];
    float s = v0 + v1 + v2;
#pragma unroll
    for (int o = 16; o > 0; o >>= 1) s += __shfl_xor_sync(0xffffffffu, s, o);
    float mean = s * (1.0f / 96.0f);
    float d0 = v0 - mean, d1 = v1 - mean, d2 = v2 - mean;
    float sq = d0 * d0 + d1 * d1 + d2 * d2;
#pragma unroll
    for (int o = 16; o > 0; o >>= 1) sq += __shfl_xor_sync(0xffffffffu, sq, o);
    float rstd = rsqrtf(sq * (1.0f / 96.0f) + 1e-5f);
    OutT* orow = out + (size_t)m * CC;
    orow[lane]      = (OutT)(d0 * rstd * g[lane]      + b[lane]);
    orow[lane + 32] = (OutT)(d1 * rstd * g[lane + 32] + b[lane + 32]);
    orow[lane + 64] = (OutT)(d2 * rstd * g[lane + 64] + b[lane + 64]);
}

__global__ void __launch_bounds__(256) k_ln1(const float* __restrict__ x,
                                             const float* __restrict__ g,
                                             const float* __restrict__ b) {
    ln_body<bf16>(x, g, b, g_ln1h, true);
}
__global__ void __launch_bounds__(256) k_ln2(const float* __restrict__ g,
                                             const float* __restrict__ b) {
    ln_body<bf16>(g_x1, g, b, g_ln2h, false);
}

// ---------------------------------------------------------------------------
// Combined additive bias
// ---------------------------------------------------------------------------
__global__ void __launch_bounds__(256) k_comb(const float* __restrict__ mask,
                                              const int* __restrict__ ridx,
                                              const float* __restrict__ table) {
    int wh = blockIdx.x;
    int widx = wh / 3, head = wh - widx * 3;
    const int NN = NTOK * NTOK;
    float* dst = g_comb + (size_t)wh * NN;
    const float* msk = mask + (size_t)widx * NN;
    for (int idx = threadIdx.x; idx < NN; idx += 256)
        dst[idx] = msk[idx] + table[ridx[idx] * NHH + head];
}

// ---------------------------------------------------------------------------
// BF16 tensor-core GEMM: C[m][n] = sum_k A[m][k]*W[n][k]
// 128x96 block tile, BK=96, 8 warps (4m x 2n), warp tile 32x48 (2x6 mma)
// ---------------------------------------------------------------------------
__device__ __forceinline__ void mma_bf16(float* c, const uint32_t* a, const uint32_t* b) {
    asm volatile(
        "mma.sync.aligned.m16n8k16.row.col.f32.bf16.bf16.f32 "
        "{%0,%1,%2,%3}, {%4,%5,%6,%7}, {%8,%9}, {%0,%1,%2,%3};"
        : "+f"(c[0]), "+f"(c[1]), "+f"(c[2]), "+f"(c[3])
        : "r"(a[0]), "r"(a[1]), "r"(a[2]), "r"(a[3]), "r"(b[0]), "r"(b[1]));
}

template <int K, typename Epi>
__device__ __forceinline__ void gemm_body(const bf16* __restrict__ A,
                                          const bf16* __restrict__ W,
                                          Epi epi) {
    constexpr int BK = 96;          // all K are multiples of 96
    constexpr int KP = 48;          // bf16x2 pairs per row
    constexpr int ST = 52;          // padded stride (words); 52%32=20 -> conflict-free
    __shared__ __align__(16) uint32_t As[128][ST];
    __shared__ __align__(16) uint32_t Bs[96][ST];
    const int tid = threadIdx.x;
    const int wid = tid >> 5, lane = tid & 31;
    const int warp_m = wid >> 1, warp_n = wid & 1;
    const int grp = lane >> 2, qid = lane & 3;
    const int m0 = blockIdx.y * 128;
    const int n0 = blockIdx.x * 96;

    float c[2][6][4];
#pragma unroll
    for (int i = 0; i < 2; i++)
#pragma unroll
        for (int j = 0; j < 6; j++)
#pragma unroll
            for (int e = 0; e < 4; e++) c[i][j][e] = 0.f;

    for (int k0 = 0; k0 < K; k0 += BK) {
        // A tile: 128 rows x 12 uint4 (8 bf16 each) = 1536 -> 6/thread
#pragma unroll
        for (int i = 0; i < 6; i++) {
            int idx = tid + i * 256;
            int row = idx / 12, c8 = idx - row * 12;
            uint4 v = *reinterpret_cast<const uint4*>(A + (size_t)(m0 + row) * K + k0 + c8 * 8);
            *reinterpret_cast<uint4*>(&As[row][c8 * 4]) = v;
        }
        // B tile: 96 rows x 12 uint4 = 1152 -> 4.5/thread
#pragma unroll
        for (int i = 0; i < 5; i++) {
            int idx = tid + i * 256;
            if (idx < 1152) {
                int row = idx / 12, c8 = idx - row * 12;
                uint4 v = *reinterpret_cast<const uint4*>(W + (size_t)(n0 + row) * K + k0 + c8 * 8);
                *reinterpret_cast<uint4*>(&Bs[row][c8 * 4]) = v;
            }
        }
        __syncthreads();

#pragma unroll
        for (int kk = 0; kk < KP; kk += 8) {   // 6 k16 steps
            uint32_t a[2][4], b[6][2];
#pragma unroll
            for (int i = 0; i < 2; i++) {
                int ar = warp_m * 32 + i * 16 + grp;
                a[i][0] = As[ar][kk + qid];
                a[i][1] = As[ar + 8][kk + qid];
                a[i][2] = As[ar][kk + qid + 4];
                a[i][3] = As[ar + 8][kk + qid + 4];
            }
#pragma unroll
            for (int j = 0; j < 6; j++) {
                int br = warp_n * 48 + j * 8 + grp;
                b[j][0] = Bs[br][kk + qid];
                b[j][1] = Bs[br][kk + qid + 4];
            }
#pragma unroll
            for (int i = 0; i < 2; i++)
#pragma unroll
                for (int j = 0; j < 6; j++)
                    mma_bf16(c[i][j], a[i], b[j]);
        }
        __syncthreads();
    }

    // epilogue: pairs (n even, n+1)
#pragma unroll
    for (int i = 0; i < 2; i++) {
        int r0 = m0 + warp_m * 32 + i * 16 + grp;
#pragma unroll
        for (int j = 0; j < 6; j++) {
            int cn = n0 + warp_n * 48 + j * 8 + qid * 2;
            epi(r0,     cn, c[i][j][0], c[i][j][1]);
            epi(r0 + 8, cn, c[i][j][2], c[i][j][3]);
        }
    }
}

// ------------------------- epilogues ---------------------------------------
struct QkvEpi {
    const float* bias;
    __device__ void operator()(int m, int n, float v0, float v1) const {
        float a = v0 + bias[n], b = v1 + bias[n + 1];
        int which = n / 96; int rem = n - which * 96;
        int head = rem >> 5; int d = rem & 31;              // d even
        int win = m / NTOK; int tok = m - win * NTOK;
        size_t off = ((size_t)(win * 3 + head) * NTOK + tok) * HDD + d;
        if (which == 0) {
            a *= 0.17677669529663689f; b *= 0.17677669529663689f;
            *reinterpret_cast<bf162*>(g_qh + off) = __floats2bfloat162_rn(a, b);
        } else if (which == 1) {
            *reinterpret_cast<bf162*>(g_kh + off) = __floats2bfloat162_rn(a, b);
        } else {
            *reinterpret_cast<bf162*>(g_vh + off) = __floats2bfloat162_rn(a, b);
        }
    }
};

struct ProjEpi {
    const float* x;
    const float* pb;
    __device__ void operator()(int m, int n, float v0, float v1) const {
        int src = rowsrc(m);
        size_t o = (size_t)src * CC + n;
        float2 xv = *reinterpret_cast<const float2*>(x + o);
        float2 r = make_float2(xv.x + v0 + pb[n], xv.y + v1 + pb[n + 1]);
        *reinterpret_cast<float2*>(g_x1 + o) = r;
    }
};

struct Fc1Epi {
    const float* fb;
    __device__ void operator()(int m, int n, float v0, float v1) const {
        float a = v0 + fb[n], b = v1 + fb[n + 1];
        a = 0.5f * a * (1.0f + erff(a * 0.70710678118654752f));
        b = 0.5f * b * (1.0f + erff(b * 0.70710678118654752f));
        *reinterpret_cast<bf162*>(g_h1h + (size_t)m * HIDD + n) = __floats2bfloat162_rn(a, b);
    }
};

struct Fc2Epi {
    const float* fb;
    float* out;
    __device__ void operator()(int m, int n, float v0, float v1) const {
        size_t o = (size_t)m * CC + n;
        float2 xv = *reinterpret_cast<const float2*>(g_x1 + o);
        float2 r = make_float2(xv.x + v0 + fb[n], xv.y + v1 + fb[n + 1]);
        *reinterpret_cast<float2*>(out + o) = r;
    }
};

// ------------------------- GEMM wrappers -----------------------------------
__global__ void __launch_bounds__(256) k_gemm_qkv(const float* __restrict__ bias) {
    gemm_body<96>(g_ln1h, g_wqkv, QkvEpi{bias});
}
__global__ void __launch_bounds__(256) k_gemm_proj(const float* __restrict__ pb,
                                                   const float* __restrict__ x) {
    gemm_body<96>(g_atth, g_wproj, ProjEpi{x, pb});
}
__global__ void __launch_bounds__(256) k_gemm_fc1(const float* __restrict__ fb) {
    gemm_body<96>(g_ln2h, g_wfc1, Fc1Epi{fb});
}
__global__ void __launch_bounds__(256) k_gemm_fc2(const float* __restrict__ fb,
                                                  float* __restrict__ out) {
    gemm_body<384>(g_h1h, g_wfc2, Fc2Epi{fb, out});
}

// ---------------------------------------------------------------------------
// Attention: one block per (window, head), 64 threads, fp32 math, bf16 I/O
// ---------------------------------------------------------------------------
__global__ void __launch_bounds__(64) k_attn() {
    int bh = blockIdx.x;
    int win = bh / 3, head = bh - win * 3;
    int widx = win & 255;

    __shared__ __align__(16) float Ks[NTOK * 32];
    __shared__ __align__(16) float Vs[NTOK * 32];
    __shared__ __align__(16) float Ps[NTOK * 51];
    __shared__ __align__(16) float Os[NTOK * 33];

    const size_t base = (size_t)bh * (NTOK * HDD);
    const int tid = threadIdx.x;

    // load q/k/v (bf16, 16B granules: 196 uint4 per tensor)
    const uint4* qp = reinterpret_cast<const uint4*>(g_qh + base);
    const uint4* kp = reinterpret_cast<const uint4*>(g_kh + base);
    const uint4* vp = reinterpret_cast<const uint4*>(g_vh + base);
    for (int idx = tid; idx < 196; idx += 64) {
        int row = idx >> 2, seg = idx & 3;
        uint4 qv = qp[idx], kv = kp[idx], vv = vp[idx];
        const bf162* q2 = reinterpret_cast<const bf162*>(&qv);
        const bf162* k2 = reinterpret_cast<const bf162*>(&kv);
        const bf162* v2 = reinterpret_cast<const bf162*>(&vv);
        float* qd = Os + row * 33 + seg * 8;
        float* kd = Ks + row * 32 + seg * 8;
        float* vd = Vs + row * 32 + seg * 8;
#pragma unroll
        for (int t = 0; t < 4; t++) {
            float2 f;
            f = __bfloat1622float2(q2[t]); qd[2 * t] = f.x; qd[2 * t + 1] = f.y;
            f = __bfloat1622float2(k2[t]); kd[2 * t] = f.x; kd[2 * t + 1] = f.y;
            f = __bfloat1622float2(v2[t]); vd[2 * t] = f.x; vd[2 * t + 1] = f.y;
        }
    }
    const float* cp = g_comb + (size_t)(widx * 3 + head) * (NTOK * NTOK);
    for (int idx = tid; idx < NTOK * NTOK; idx += 64) {
        int i = idx / NTOK, j = idx - i * NTOK;
        Ps[i * 51 + j] = cp[idx];
    }
    __syncthreads();

    int i = tid;
    if (i < NTOK) {
        float q[32];
#pragma unroll
        for (int d = 0; d < 32; d++) q[d] = Os[i * 33 + d];

        float mx = -1e30f;
        for (int j = 0; j < NTOK; j++) {
            float s = Ps[i * 51 + j];
            const float4* kr = reinterpret_cast<const float4*>(Ks + j * 32);
#pragma unroll
            for (int d4 = 0; d4 < 8; d4++) {
                float4 kv = kr[d4];
                s += q[4 * d4] * kv.x + q[4 * d4 + 1] * kv.y
                   + q[4 * d4 + 2] * kv.z + q[4 * d4 + 3] * kv.w;
            }
            Ps[i * 51 + j] = s;
            mx = fmaxf(mx, s);
        }
        float sum = 0.f;
        for (int j = 0; j < NTOK; j++) {
            float e = __expf(Ps[i * 51 + j] - mx);
            Ps[i * 51 + j] = e;
            sum += e;
        }
        float inv = 1.0f / sum;

        float o[32];
#pragma unroll
        for (int d = 0; d < 32; d++) o[d] = 0.f;
        for (int j = 0; j < NTOK; j++) {
            float p = Ps[i * 51 + j];
            const float4* vr = reinterpret_cast<const float4*>(Vs + j * 32);
#pragma unroll
            for (int d4 = 0; d4 < 8; d4++) {
                float4 vv = vr[d4];
                o[4 * d4]     += p * vv.x;
                o[4 * d4 + 1] += p * vv.y;
                o[4 * d4 + 2] += p * vv.z;
                o[4 * d4 + 3] += p * vv.w;
            }
        }
#pragma unroll
        for (int d = 0; d < 32; d++) Os[i * 33 + d] = o[d] * inv;
    }
    __syncthreads();

    bf16* op = g_atth + (size_t)win * (NTOK * CC) + head * HDD;
    for (int idx = tid; idx < NTOK * 16; idx += 64) {
        int i2 = idx >> 4, dp = idx & 15;
        float a = Os[i2 * 33 + dp * 2], b = Os[i2 * 33 + dp * 2 + 1];
        *reinterpret_cast<bf162*>(op + i2 * CC + dp * 2) = __floats2bfloat162_rn(a, b);
    }
}

// ---------------------------------------------------------------------------
// Launch
// ---------------------------------------------------------------------------
extern "C" void kernel_launch(void* const* d_in, const int* in_sizes, int n_in,
                              void* d_out, int out_size) {
    const float* x         = (const float*)d_in[0];
    const float* attn_mask = (const float*)d_in[1];
    const int*   rel_index = (const int*)  d_in[2];
    const float* n1g       = (const float*)d_in[3];
    const float* n1b       = (const float*)d_in[4];
    const float* qkv_w     = (const float*)d_in[5];
    const float* qkv_b     = (const float*)d_in[6];
    const float* proj_w    = (const float*)d_in[7];
    const float* proj_b    = (const float*)d_in[8];
    const float* tbl       = (const float*)d_in[9];
    const float* n2g       = (const float*)d_in[10];
    const float* n2b       = (const float*)d_in[11];
    const float* fc1_w     = (const float*)d_in[12];
    const float* fc1_b     = (const float*)d_in[13];
    const float* fc2_w     = (const float*)d_in[14];
    const float* fc2_b     = (const float*)d_in[15];
    float* out = (float*)d_out;

    k_prep<<<432, 256>>>(qkv_w, proj_w, fc1_w, fc2_w);
    k_ln1 <<<MTOK / 8, 256>>>(x, n1g, n1b);
    k_comb<<<256 * NHH, 256>>>(attn_mask, rel_index, tbl);
    k_gemm_qkv <<<dim3(3, MTOK / 128), 256>>>(qkv_b);
    k_attn<<<NWIN * NHH, 64>>>();
    k_gemm_proj<<<dim3(1, MTOK / 128), 256>>>(proj_b, x);
    k_ln2 <<<MTOK / 8, 256>>>(n2g, n2b);
    k_gemm_fc1 <<<dim3(4, MTOK / 128), 256>>>(fc1_b);
    k_gemm_fc2 <<<dim3(1, MTOK / 128), 256>>>(fc2_b, out);
}